// round 3
// baseline (speedup 1.0000x reference)
#include <cuda_runtime.h>

#define BB 4
#define CCH 64
#define HH 256
#define WWD 256
#define HWW (HH*WWD)
#define NHEADS 4
#define DDIM 16
#define WHF 128
#define NSQ (HH*WHF)
#define C2 128
#define C4 256

typedef unsigned long long u64;

// ---------------- scratch (static device allocations only) ----------------
__device__ float g_q1[BB*CCH*HWW];
__device__ float g_k1[BB*CCH*HWW];
__device__ float g_v1[BB*CCH*HWW];
__device__ float g_qs[BB*CCH*NSQ];
__device__ float g_ks[BB*CCH*NSQ];
__device__ float g_vs[BB*CCH*NSQ];
__device__ float g_ctx[BB*NHEADS*DDIM*DDIM];
__device__ float g_att[BB*CCH*NSQ];      // squeezed att (b, C, H, W/2)
__device__ float g_attn[BB*C2*HWW];
__device__ float g_m1[BB*C4*HWW];
__device__ float g_m2[BB*C4*HWW];

__device__ __forceinline__ float gelu_f(float x) {
    return 0.5f * x * (1.0f + erff(x * 0.7071067811865476f));
}

// ---- packed f32x2 helpers ----
__device__ __forceinline__ void fma2(u64& d, u64 a, u64 b) {
    asm("fma.rn.f32x2 %0, %1, %2, %0;" : "+l"(d) : "l"(a), "l"(b));
}
__device__ __forceinline__ u64 pk(float lo, float hi) {
    u64 r;
    asm("mov.b64 %0, {%1, %2};" : "=l"(r)
        : "r"(__float_as_uint(lo)), "r"(__float_as_uint(hi)));
    return r;
}
__device__ __forceinline__ float2 upk(u64 v) {
    unsigned int a, b;
    asm("mov.b64 {%0, %1}, %2;" : "=r"(a), "=r"(b) : "l"(v));
    return make_float2(__uint_as_float(a), __uint_as_float(b));
}

// ---------------- 1x1 conv as tiled GEMM (f32x2 packed) ----------------
// tile: 64 co x 128 px, K-chunks of 32. thread: 4 co x 8 px (two 4-px groups 64 apart).
// ACT: 0 none, 1 gelu, 2 add-residual. MASK: 0 none, 1 keep (i+j)%2==0, 2 keep ==1.
template<int CIN, int COUT, int ACT, int MASK>
__global__ __launch_bounds__(256) void conv1x1_kernel(
    const float* __restrict__ in, const float* __restrict__ wt,
    const float* __restrict__ bias, const float* __restrict__ res,
    float* __restrict__ out)
{
    __shared__ float2 Wsd[32*64];   // [ci][co], weight duplicated (w,w)
    __shared__ float  Xs[32][128];  // [ci][px]

    const int p0  = blockIdx.x * 128;
    const int cot = blockIdx.y;
    const int b   = blockIdx.z;
    const int tid = threadIdx.x;

    const int px0 = (tid & 15) * 4;   // 4 px + 4 px at +64
    const int co0 = (tid >> 4) * 4;

    u64 acc2[4][4];
    #pragma unroll
    for (int u = 0; u < 4; u++)
        #pragma unroll
        for (int v = 0; v < 4; v++) acc2[u][v] = 0ull;

    for (int k0 = 0; k0 < CIN; k0 += 32) {
        __syncthreads();
        // weights duplicated: consecutive threads -> consecutive co (conflict-free STS.64)
        #pragma unroll
        for (int q = tid; q < 2048; q += 256) {
            int co = q & 63;
            int ci = q >> 6;
            float wv = wt[(size_t)(cot*64 + co) * CIN + k0 + ci];
            Wsd[ci*64 + co] = make_float2(wv, wv);
        }
        // X tile, float4 coalesced
        #pragma unroll
        for (int q = tid; q < 1024; q += 256) {
            int ci = q >> 5;
            int f4 = q & 31;
            int p  = p0 + f4 * 4;
            float4 v = *reinterpret_cast<const float4*>(
                in + (size_t)(b * CIN + k0 + ci) * HWW + p);
            if (MASK) {
                int i  = p >> 8;
                int j  = p & 255;
                int pb = (i + j) & 1;
                int kp = (MASK == 1) ? pb : (pb ^ 1);
                if (kp == 0) { v.y = 0.f; v.w = 0.f; }
                else         { v.x = 0.f; v.z = 0.f; }
            }
            *reinterpret_cast<float4*>(&Xs[ci][f4*4]) = v;
        }
        __syncthreads();

        #pragma unroll
        for (int k = 0; k < 32; k++) {
            u64 xp0 = *reinterpret_cast<const u64*>(&Xs[k][px0]);
            u64 xp1 = *reinterpret_cast<const u64*>(&Xs[k][px0 + 2]);
            u64 xp2 = *reinterpret_cast<const u64*>(&Xs[k][px0 + 64]);
            u64 xp3 = *reinterpret_cast<const u64*>(&Xs[k][px0 + 66]);
            #pragma unroll
            for (int u = 0; u < 4; u++) {
                u64 wd = *reinterpret_cast<const u64*>(&Wsd[k*64 + co0 + u]);
                fma2(acc2[u][0], wd, xp0);
                fma2(acc2[u][1], wd, xp1);
                fma2(acc2[u][2], wd, xp2);
                fma2(acc2[u][3], wd, xp3);
            }
        }
    }

    #pragma unroll
    for (int u = 0; u < 4; u++) {
        int co = cot*64 + co0 + u;
        float bb = bias[co];
        size_t base = (size_t)(b * COUT + co) * HWW + p0;
        #pragma unroll
        for (int g = 0; g < 2; g++) {
            size_t off = base + px0 + g * 64;
            float2 pa = upk(acc2[u][g*2 + 0]);
            float2 pb = upk(acc2[u][g*2 + 1]);
            float vals[4] = {pa.x, pa.y, pb.x, pb.y};
            float4 o;
            float* ov = reinterpret_cast<float*>(&o);
            #pragma unroll
            for (int v = 0; v < 4; v++) {
                float val = vals[v] + bb;
                if (ACT == 1) val = gelu_f(val);
                if (ACT == 2) val += res[off + v];
                ov[v] = val;
            }
            *reinterpret_cast<float4*>(out + off) = o;
        }
    }
}

// ---------------- depthwise 3x3 fused with checkerboard squeeze ----------------
__global__ void dw_squeeze_kernel(const float* __restrict__ in,
                                  const float* __restrict__ wt,
                                  const float* __restrict__ bias,
                                  float* __restrict__ out, int anchor)
{
    int id = blockIdx.x * blockDim.x + threadIdx.x;
    if (id >= BB*CCH*NSQ) return;
    int j = id & (WHF-1);
    int i = (id >> 7) & (HH-1);
    int c = (id >> 15) & (CCH-1);
    int b = id >> 21;
    int x = 2*j + (anchor ? (1 - (i & 1)) : (i & 1));
    float w[9];
    #pragma unroll
    for (int t = 0; t < 9; t++) w[t] = __ldg(&wt[c*9 + t]);
    float acc = bias[c];
    const float* base = in + (size_t)(b*CCH + c) * HWW;
    #pragma unroll
    for (int dy = -1; dy <= 1; dy++) {
        int yy = i + dy;
        if (yy < 0 || yy >= HH) continue;
        #pragma unroll
        for (int dx = -1; dx <= 1; dx++) {
            int xx = x + dx;
            if (xx < 0 || xx >= WWD) continue;
            acc += w[(dy+1)*3 + (dx+1)] * base[yy*WWD + xx];
        }
    }
    out[id] = acc;
}

// ---------------- softmax over n per (b,c) row, in place ----------------
__global__ __launch_bounds__(512) void softmax_k_kernel(float* __restrict__ data)
{
    __shared__ float sm[16];
    float* ptr = data + (size_t)blockIdx.x * NSQ;
    int tid = threadIdx.x;

    float m = -1e30f;
    for (int idx = tid; idx < NSQ; idx += 512) m = fmaxf(m, ptr[idx]);
    #pragma unroll
    for (int o = 16; o; o >>= 1) m = fmaxf(m, __shfl_xor_sync(0xffffffffu, m, o));
    if ((tid & 31) == 0) sm[tid >> 5] = m;
    __syncthreads();
    if (tid < 32) {
        float t = (tid < 16) ? sm[tid] : -1e30f;
        #pragma unroll
        for (int o = 8; o; o >>= 1) t = fmaxf(t, __shfl_xor_sync(0xffffffffu, t, o));
        if (tid == 0) sm[0] = t;
    }
    __syncthreads();
    m = sm[0];
    __syncthreads();

    float s = 0.f;
    for (int idx = tid; idx < NSQ; idx += 512) s += expf(ptr[idx] - m);
    #pragma unroll
    for (int o = 16; o; o >>= 1) s += __shfl_xor_sync(0xffffffffu, s, o);
    if ((tid & 31) == 0) sm[tid >> 5] = s;
    __syncthreads();
    if (tid < 32) {
        float t = (tid < 16) ? sm[tid] : 0.f;
        #pragma unroll
        for (int o = 8; o; o >>= 1) t += __shfl_xor_sync(0xffffffffu, t, o);
        if (tid == 0) sm[0] = t;
    }
    __syncthreads();
    float inv = 1.f / sm[0];
    for (int idx = tid; idx < NSQ; idx += 512) ptr[idx] = expf(ptr[idx] - m) * inv;
}

// ---------------- ctx = k_sm @ v_s^T  (16x16 per (b,head)) ----------------
__global__ void ctx_zero_kernel() {
    int id = blockIdx.x * blockDim.x + threadIdx.x;
    if (id < BB*NHEADS*DDIM*DDIM) g_ctx[id] = 0.f;
}

__global__ __launch_bounds__(256) void ctx_kernel()
{
    __shared__ float ka[16][129];
    __shared__ float va[16][129];
    int bh = blockIdx.x;
    int chunk = blockIdx.y;
    int b = bh >> 2, h = bh & 3;
    int tid = threadIdx.x;
    int d = tid >> 4, e = tid & 15;
    const float* kbase = g_ks + (size_t)(b*CCH + h*16) * NSQ;
    const float* vbase = g_vs + (size_t)(b*CCH + h*16) * NSQ;
    float acc = 0.f;
    for (int sub = 0; sub < 8; sub++) {
        int n0 = chunk * 1024 + sub * 128;
        __syncthreads();
        #pragma unroll
        for (int q = tid; q < 2048; q += 256) {
            int r = q >> 7, t = q & 127;
            ka[r][t] = kbase[(size_t)r * NSQ + n0 + t];
            va[r][t] = vbase[(size_t)r * NSQ + n0 + t];
        }
        __syncthreads();
        #pragma unroll
        for (int t = 0; t < 128; t++) acc += ka[d][t] * va[e][t];
    }
    atomicAdd(&g_ctx[bh*256 + tid], acc);
}

// ---------------- q softmax(over d) + ctx apply -> SQUEEZED att ----------------
__global__ __launch_bounds__(256) void att_kernel()
{
    __shared__ float cs[16][17];
    int bh = blockIdx.y;
    int b = bh >> 2, h = bh & 3;
    int tid = threadIdx.x;
    int n = blockIdx.x * 256 + tid;
    cs[tid >> 4][tid & 15] = g_ctx[bh*256 + tid];
    __syncthreads();

    const float* qb = g_qs + (size_t)(b*CCH + h*16) * NSQ + n;
    float p[16];
    float m = -1e30f;
    #pragma unroll
    for (int d = 0; d < 16; d++) { p[d] = qb[(size_t)d * NSQ]; m = fmaxf(m, p[d]); }
    float s = 0.f;
    #pragma unroll
    for (int d = 0; d < 16; d++) { p[d] = expf(p[d] - m); s += p[d]; }
    float inv = 1.f / s;

    int i = n >> 7, j = n & 127;
    #pragma unroll
    for (int e = 0; e < 16; e++) {
        float a = 0.f;
        #pragma unroll
        for (int d = 0; d < 16; d++) a += cs[d][e] * p[d];
        a *= inv;
        // squeezed layout: att_s[b][c][i][j] = att value at x = 2j + (i&1)
        g_att[((size_t)(b*CCH + h*16 + e) * HH + i) * WHF + j] = a;
    }
}

// ---------------- 5x5 conv 64 -> 128, pad 2, checkerboard-sparse input ----------------
// Input is squeezed att: nonzero full-grid position (yy, xx) iff (yy+xx) even,
// value = att_s[yy][(xx - (yy&1))/2]. Only active taps computed (~half the FMAs),
// accumulated pairwise with fma.rn.f32x2 (outputs v and v+2 share taps).
__global__ __launch_bounds__(256) void conv5_kernel(
    const float* __restrict__ wt, const float* __restrict__ bias)
{
    __shared__ float  xs[8][68];     // squeezed rows with halo
    __shared__ float2 wsd[16*25];    // weights duplicated (w,w)
    int X0  = blockIdx.x * 128;
    int y0  = blockIdx.y * 4;
    int b   = blockIdx.z >> 3;
    int cot = blockIdx.z & 7;
    int tid = threadIdx.x;
    int cg  = tid & 3;               // 4 co each -> warp-uniform py below
    int px0 = ((tid >> 2) & 15) * 8; // 0..120
    int py  = tid >> 6;              // 0..3, uniform per warp
    int th  = px0 >> 1;
    int jb  = X0/2 - 1;

    // acc2[u][m]: m=0 -> (v0,v2), m=1 -> (v1,v3), m=2 -> (v4,v6), m=3 -> (v5,v7)
    u64 acc2[4][4];
    #pragma unroll
    for (int u = 0; u < 4; u++)
        #pragma unroll
        for (int m = 0; m < 4; m++) acc2[u][m] = 0ull;

    for (int ci = 0; ci < 64; ci++) {
        __syncthreads();
        const float* ib = g_att + (size_t)(b*CCH + ci) * NSQ;
        for (int q = tid; q < 544; q += 256) {
            int r = q / 68, t = q - r * 68;
            int yy = y0 + r - 2;
            int jj = jb + t;
            float v = 0.f;
            if (yy >= 0 && yy < HH && jj >= 0 && jj < WHF) v = ib[yy*WHF + jj];
            xs[r][t] = v;
        }
        for (int q = tid; q < 400; q += 256) {
            int co = q / 25, tap = q - co * 25;
            float wv = wt[((size_t)(cot*16 + co) * 64 + ci) * 25 + tap];
            wsd[co*25 + tap] = make_float2(wv, wv);
        }
        __syncthreads();

        #pragma unroll
        for (int dy = 0; dy < 5; dy++) {
            int r = py + dy;
            float4 a4 = *reinterpret_cast<const float4*>(&xs[r][th]);
            float4 b4 = *reinterpret_cast<const float4*>(&xs[r][th + 4]);
            float rv[8] = {a4.x,a4.y,a4.z,a4.w, b4.x,b4.y,b4.z,b4.w};
            u64 rp[5];
            #pragma unroll
            for (int t = 0; t < 5; t++) rp[t] = pk(rv[t], rv[t+1]);

            const u64* wrow = reinterpret_cast<const u64*>(wsd) + (cg*4)*25 + dy*5;
            if ((r & 1) == 0) {   // input-row parity 0: taps with (v+dx) even
                #pragma unroll
                for (int u = 0; u < 4; u++) {
                    const u64* wr = wrow + u*25;
                    // v even (pairs base 0,4), dx in {0,2,4}
                    #pragma unroll
                    for (int dx = 0; dx < 5; dx += 2) {
                        u64 w = wr[dx];
                        fma2(acc2[u][0], w, rp[dx>>1]);
                        fma2(acc2[u][2], w, rp[(dx>>1) + 2]);
                    }
                    // v odd (pairs base 1,5), dx in {1,3}
                    #pragma unroll
                    for (int dx = 1; dx < 5; dx += 2) {
                        u64 w = wr[dx];
                        fma2(acc2[u][1], w, rp[(1+dx)>>1]);
                        fma2(acc2[u][3], w, rp[(5+dx)>>1]);
                    }
                }
            } else {              // parity 1: taps with (v+dx) odd
                #pragma unroll
                for (int u = 0; u < 4; u++) {
                    const u64* wr = wrow + u*25;
                    // v even, dx in {1,3}
                    #pragma unroll
                    for (int dx = 1; dx < 5; dx += 2) {
                        u64 w = wr[dx];
                        fma2(acc2[u][0], w, rp[(dx-1)>>1]);
                        fma2(acc2[u][2], w, rp[(dx+3)>>1]);
                    }
                    // v odd, dx in {0,2,4}
                    #pragma unroll
                    for (int dx = 0; dx < 5; dx += 2) {
                        u64 w = wr[dx];
                        fma2(acc2[u][1], w, rp[dx>>1]);
                        fma2(acc2[u][3], w, rp[(dx>>1) + 2]);
                    }
                }
            }
        }
    }

    #pragma unroll
    for (int u = 0; u < 4; u++) {
        int co = cot*16 + cg*4 + u;
        float bb = bias[co];
        float2 q0 = upk(acc2[u][0]);  // v0, v2
        float2 q1 = upk(acc2[u][1]);  // v1, v3
        float2 q2 = upk(acc2[u][2]);  // v4, v6
        float2 q3 = upk(acc2[u][3]);  // v5, v7
        size_t base = ((size_t)(b*C2 + co) * HH + (y0 + py)) * WWD + X0 + px0;
        float4 o0 = make_float4(q0.x + bb, q1.x + bb, q0.y + bb, q1.y + bb);
        float4 o1 = make_float4(q2.x + bb, q3.x + bb, q2.y + bb, q3.y + bb);
        *reinterpret_cast<float4*>(&g_attn[base])     = o0;
        *reinterpret_cast<float4*>(&g_attn[base + 4]) = o1;
    }
}

// ---------------- depthwise 3x3 (256 ch) + gelu ----------------
__global__ void dw_gelu_kernel(const float* __restrict__ in,
                               const float* __restrict__ wt,
                               const float* __restrict__ bias,
                               float* __restrict__ out)
{
    int id = blockIdx.x * blockDim.x + threadIdx.x;
    if (id >= BB*C4*HWW) return;
    int j = id & 255;
    int i = (id >> 8) & 255;
    int c = (id >> 16) & 255;
    int b = id >> 24;
    float w[9];
    #pragma unroll
    for (int t = 0; t < 9; t++) w[t] = __ldg(&wt[c*9 + t]);
    float acc = bias[c];
    const float* base = in + (size_t)(b*C4 + c) * HWW;
    #pragma unroll
    for (int dy = -1; dy <= 1; dy++) {
        int yy = i + dy;
        if (yy < 0 || yy >= HH) continue;
        #pragma unroll
        for (int dx = -1; dx <= 1; dx++) {
            int xx = j + dx;
            if (xx < 0 || xx >= WWD) continue;
            acc += w[(dy+1)*3 + (dx+1)] * base[yy*WWD + xx];
        }
    }
    out[id] = gelu_f(acc);
}

// ---------------- launch ----------------
extern "C" void kernel_launch(void* const* d_in, const int* in_sizes, int n_in,
                              void* d_out, int out_size)
{
    const float* x1   = (const float*)d_in[0];
    const float* x2   = (const float*)d_in[1];
    const float* q1_w = (const float*)d_in[2];
    const float* q1_b = (const float*)d_in[3];
    const float* q2_w = (const float*)d_in[4];
    const float* q2_b = (const float*)d_in[5];
    const float* k1_w = (const float*)d_in[6];
    const float* k1_b = (const float*)d_in[7];
    const float* k2_w = (const float*)d_in[8];
    const float* k2_b = (const float*)d_in[9];
    const float* v1_w = (const float*)d_in[10];
    const float* v1_b = (const float*)d_in[11];
    const float* v2_w = (const float*)d_in[12];
    const float* v2_b = (const float*)d_in[13];
    const float* r_w  = (const float*)d_in[14];
    const float* r_b  = (const float*)d_in[15];
    const float* m1_w = (const float*)d_in[16];
    const float* m1_b = (const float*)d_in[17];
    const float* m2_w = (const float*)d_in[18];
    const float* m2_b = (const float*)d_in[19];
    const float* m3_w = (const float*)d_in[20];
    const float* m3_b = (const float*)d_in[21];
    float* out = (float*)d_out;

    float *p_q1, *p_k1, *p_v1, *p_qs, *p_ks, *p_vs, *p_attn, *p_m1, *p_m2;
    cudaGetSymbolAddress((void**)&p_q1, g_q1);
    cudaGetSymbolAddress((void**)&p_k1, g_k1);
    cudaGetSymbolAddress((void**)&p_v1, g_v1);
    cudaGetSymbolAddress((void**)&p_qs, g_qs);
    cudaGetSymbolAddress((void**)&p_ks, g_ks);
    cudaGetSymbolAddress((void**)&p_vs, g_vs);
    cudaGetSymbolAddress((void**)&p_attn, g_attn);
    cudaGetSymbolAddress((void**)&p_m1, g_m1);
    cudaGetSymbolAddress((void**)&p_m2, g_m2);

    dim3 g1(HWW/128, 1, BB);
    conv1x1_kernel<64,64,0,1><<<g1, 256>>>(x1, q1_w, q1_b, nullptr, p_q1);
    conv1x1_kernel<64,64,0,2><<<g1, 256>>>(x1, k1_w, k1_b, nullptr, p_k1);
    conv1x1_kernel<64,64,0,0><<<g1, 256>>>(x2, v1_w, v1_b, nullptr, p_v1);

    int ndw = BB*CCH*NSQ;
    dw_squeeze_kernel<<<ndw/256, 256>>>(p_q1, q2_w, q2_b, p_qs, 0);
    dw_squeeze_kernel<<<ndw/256, 256>>>(p_k1, k2_w, k2_b, p_ks, 1);
    dw_squeeze_kernel<<<ndw/256, 256>>>(p_v1, v2_w, v2_b, p_vs, 1);

    softmax_k_kernel<<<BB*CCH, 512>>>(p_ks);

    ctx_zero_kernel<<<16, 256>>>();
    ctx_kernel<<<dim3(BB*NHEADS, 32), 256>>>();

    att_kernel<<<dim3(NSQ/256, BB*NHEADS), 256>>>();

    conv5_kernel<<<dim3(2, 64, 32), 256>>>(r_w, r_b);

    conv1x1_kernel<128,256,1,0><<<dim3(HWW/128, 4, BB), 256>>>(p_attn, m1_w, m1_b, nullptr, p_m1);

    dw_gelu_kernel<<<(BB*C4*HWW)/256, 256>>>(p_m1, m2_w, m2_b, p_m2);

    conv1x1_kernel<256,128,2,0><<<dim3(HWW/128, 2, BB), 256>>>(p_m2, m3_w, m3_b, p_attn, out);
}

// round 4
// speedup vs baseline: 1.0015x; 1.0015x over previous
#include <cuda_runtime.h>

#define BB 4
#define CCH 64
#define HH 256
#define WWD 256
#define HWW (HH*WWD)
#define NHEADS 4
#define DDIM 16
#define WHF 128
#define NSQ (HH*WHF)
#define C2 128
#define C4 256

typedef unsigned long long u64;

// ---------------- scratch (static device allocations only) ----------------
__device__ float g_q1[BB*CCH*HWW];
__device__ float g_k1[BB*CCH*HWW];
__device__ float g_v1[BB*CCH*HWW];
__device__ float g_qs[BB*CCH*NSQ];
__device__ float g_ks[BB*CCH*NSQ];
__device__ float g_vs[BB*CCH*NSQ];
__device__ float g_ctx[BB*NHEADS*DDIM*DDIM];
__device__ float g_att[BB*CCH*NSQ];      // squeezed att (b, C, H, W/2)
__device__ float g_attn[BB*C2*HWW];
__device__ float g_m1[BB*C4*HWW];
__device__ float g_m2[BB*C4*HWW];

__device__ __forceinline__ float gelu_f(float x) {
    return 0.5f * x * (1.0f + erff(x * 0.7071067811865476f));
}

// ---- packed f32x2 helpers ----
__device__ __forceinline__ void fma2(u64& d, u64 a, u64 b) {
    asm("fma.rn.f32x2 %0, %1, %2, %0;" : "+l"(d) : "l"(a), "l"(b));
}
__device__ __forceinline__ u64 pk(float lo, float hi) {
    u64 r;
    asm("mov.b64 %0, {%1, %2};" : "=l"(r)
        : "r"(__float_as_uint(lo)), "r"(__float_as_uint(hi)));
    return r;
}
__device__ __forceinline__ float2 upk(u64 v) {
    unsigned int a, b;
    asm("mov.b64 {%0, %1}, %2;" : "=r"(a), "=r"(b) : "l"(v));
    return make_float2(__uint_as_float(a), __uint_as_float(b));
}

// ---------------- 1x1 conv as tiled GEMM (f32x2 packed) ----------------
// tile: 64 co x 128 px, K-chunks of 32. thread: 4 co x 8 px (two 4-px groups 64 apart).
// ACT: 0 none, 1 gelu, 2 add-residual. MASK: 0 none, 1 keep (i+j)%2==0, 2 keep ==1.
template<int CIN, int COUT, int ACT, int MASK>
__global__ __launch_bounds__(256) void conv1x1_kernel(
    const float* __restrict__ in, const float* __restrict__ wt,
    const float* __restrict__ bias, const float* __restrict__ res,
    float* __restrict__ out)
{
    __shared__ float2 Wsd[32*64];   // [ci][co], weight duplicated (w,w)
    __shared__ float  Xs[32][128];  // [ci][px]

    const int p0  = blockIdx.x * 128;
    const int cot = blockIdx.y;
    const int b   = blockIdx.z;
    const int tid = threadIdx.x;

    const int px0 = (tid & 15) * 4;   // 4 px + 4 px at +64
    const int co0 = (tid >> 4) * 4;

    u64 acc2[4][4];
    #pragma unroll
    for (int u = 0; u < 4; u++)
        #pragma unroll
        for (int v = 0; v < 4; v++) acc2[u][v] = 0ull;

    for (int k0 = 0; k0 < CIN; k0 += 32) {
        __syncthreads();
        // weights duplicated: consecutive threads -> consecutive co (conflict-free STS.64)
        #pragma unroll
        for (int q = tid; q < 2048; q += 256) {
            int co = q & 63;
            int ci = q >> 6;
            float wv = wt[(size_t)(cot*64 + co) * CIN + k0 + ci];
            Wsd[ci*64 + co] = make_float2(wv, wv);
        }
        // X tile, float4 coalesced
        #pragma unroll
        for (int q = tid; q < 1024; q += 256) {
            int ci = q >> 5;
            int f4 = q & 31;
            int p  = p0 + f4 * 4;
            float4 v = *reinterpret_cast<const float4*>(
                in + (size_t)(b * CIN + k0 + ci) * HWW + p);
            if (MASK) {
                int i  = p >> 8;
                int j  = p & 255;
                int pb = (i + j) & 1;
                int kp = (MASK == 1) ? pb : (pb ^ 1);
                if (kp == 0) { v.y = 0.f; v.w = 0.f; }
                else         { v.x = 0.f; v.z = 0.f; }
            }
            *reinterpret_cast<float4*>(&Xs[ci][f4*4]) = v;
        }
        __syncthreads();

        #pragma unroll
        for (int k = 0; k < 32; k++) {
            u64 xp0 = *reinterpret_cast<const u64*>(&Xs[k][px0]);
            u64 xp1 = *reinterpret_cast<const u64*>(&Xs[k][px0 + 2]);
            u64 xp2 = *reinterpret_cast<const u64*>(&Xs[k][px0 + 64]);
            u64 xp3 = *reinterpret_cast<const u64*>(&Xs[k][px0 + 66]);
            #pragma unroll
            for (int u = 0; u < 4; u++) {
                u64 wd = *reinterpret_cast<const u64*>(&Wsd[k*64 + co0 + u]);
                fma2(acc2[u][0], wd, xp0);
                fma2(acc2[u][1], wd, xp1);
                fma2(acc2[u][2], wd, xp2);
                fma2(acc2[u][3], wd, xp3);
            }
        }
    }

    #pragma unroll
    for (int u = 0; u < 4; u++) {
        int co = cot*64 + co0 + u;
        float bb = bias[co];
        size_t base = (size_t)(b * COUT + co) * HWW + p0;
        #pragma unroll
        for (int g = 0; g < 2; g++) {
            size_t off = base + px0 + g * 64;
            float2 pa = upk(acc2[u][g*2 + 0]);
            float2 pb = upk(acc2[u][g*2 + 1]);
            float vals[4] = {pa.x, pa.y, pb.x, pb.y};
            float4 o;
            float* ov = reinterpret_cast<float*>(&o);
            #pragma unroll
            for (int v = 0; v < 4; v++) {
                float val = vals[v] + bb;
                if (ACT == 1) val = gelu_f(val);
                if (ACT == 2) val += res[off + v];
                ov[v] = val;
            }
            *reinterpret_cast<float4*>(out + off) = o;
        }
    }
}

// ---------------- depthwise 3x3 fused with checkerboard squeeze ----------------
__global__ void dw_squeeze_kernel(const float* __restrict__ in,
                                  const float* __restrict__ wt,
                                  const float* __restrict__ bias,
                                  float* __restrict__ out, int anchor)
{
    int id = blockIdx.x * blockDim.x + threadIdx.x;
    if (id >= BB*CCH*NSQ) return;
    int j = id & (WHF-1);
    int i = (id >> 7) & (HH-1);
    int c = (id >> 15) & (CCH-1);
    int b = id >> 21;
    int x = 2*j + (anchor ? (1 - (i & 1)) : (i & 1));
    float w[9];
    #pragma unroll
    for (int t = 0; t < 9; t++) w[t] = __ldg(&wt[c*9 + t]);
    float acc = bias[c];
    const float* base = in + (size_t)(b*CCH + c) * HWW;
    #pragma unroll
    for (int dy = -1; dy <= 1; dy++) {
        int yy = i + dy;
        if (yy < 0 || yy >= HH) continue;
        #pragma unroll
        for (int dx = -1; dx <= 1; dx++) {
            int xx = x + dx;
            if (xx < 0 || xx >= WWD) continue;
            acc += w[(dy+1)*3 + (dx+1)] * base[yy*WWD + xx];
        }
    }
    out[id] = acc;
}

// ---------------- softmax over n per (b,c) row, in place ----------------
__global__ __launch_bounds__(512) void softmax_k_kernel(float* __restrict__ data)
{
    __shared__ float sm[16];
    float* ptr = data + (size_t)blockIdx.x * NSQ;
    int tid = threadIdx.x;

    float m = -1e30f;
    for (int idx = tid; idx < NSQ; idx += 512) m = fmaxf(m, ptr[idx]);
    #pragma unroll
    for (int o = 16; o; o >>= 1) m = fmaxf(m, __shfl_xor_sync(0xffffffffu, m, o));
    if ((tid & 31) == 0) sm[tid >> 5] = m;
    __syncthreads();
    if (tid < 32) {
        float t = (tid < 16) ? sm[tid] : -1e30f;
        #pragma unroll
        for (int o = 8; o; o >>= 1) t = fmaxf(t, __shfl_xor_sync(0xffffffffu, t, o));
        if (tid == 0) sm[0] = t;
    }
    __syncthreads();
    m = sm[0];
    __syncthreads();

    float s = 0.f;
    for (int idx = tid; idx < NSQ; idx += 512) s += expf(ptr[idx] - m);
    #pragma unroll
    for (int o = 16; o; o >>= 1) s += __shfl_xor_sync(0xffffffffu, s, o);
    if ((tid & 31) == 0) sm[tid >> 5] = s;
    __syncthreads();
    if (tid < 32) {
        float t = (tid < 16) ? sm[tid] : 0.f;
        #pragma unroll
        for (int o = 8; o; o >>= 1) t += __shfl_xor_sync(0xffffffffu, t, o);
        if (tid == 0) sm[0] = t;
    }
    __syncthreads();
    float inv = 1.f / sm[0];
    for (int idx = tid; idx < NSQ; idx += 512) ptr[idx] = expf(ptr[idx] - m) * inv;
}

// ---------------- ctx = k_sm @ v_s^T  (16x16 per (b,head)) ----------------
__global__ void ctx_zero_kernel() {
    int id = blockIdx.x * blockDim.x + threadIdx.x;
    if (id < BB*NHEADS*DDIM*DDIM) g_ctx[id] = 0.f;
}

__global__ __launch_bounds__(256) void ctx_kernel()
{
    __shared__ float ka[16][129];
    __shared__ float va[16][129];
    int bh = blockIdx.x;
    int chunk = blockIdx.y;
    int b = bh >> 2, h = bh & 3;
    int tid = threadIdx.x;
    int d = tid >> 4, e = tid & 15;
    const float* kbase = g_ks + (size_t)(b*CCH + h*16) * NSQ;
    const float* vbase = g_vs + (size_t)(b*CCH + h*16) * NSQ;
    float acc = 0.f;
    for (int sub = 0; sub < 8; sub++) {
        int n0 = chunk * 1024 + sub * 128;
        __syncthreads();
        #pragma unroll
        for (int q = tid; q < 2048; q += 256) {
            int r = q >> 7, t = q & 127;
            ka[r][t] = kbase[(size_t)r * NSQ + n0 + t];
            va[r][t] = vbase[(size_t)r * NSQ + n0 + t];
        }
        __syncthreads();
        #pragma unroll
        for (int t = 0; t < 128; t++) acc += ka[d][t] * va[e][t];
    }
    atomicAdd(&g_ctx[bh*256 + tid], acc);
}

// ---------------- q softmax(over d) + ctx apply -> SQUEEZED att ----------------
__global__ __launch_bounds__(256) void att_kernel()
{
    __shared__ float cs[16][17];
    int bh = blockIdx.y;
    int b = bh >> 2, h = bh & 3;
    int tid = threadIdx.x;
    int n = blockIdx.x * 256 + tid;
    cs[tid >> 4][tid & 15] = g_ctx[bh*256 + tid];
    __syncthreads();

    const float* qb = g_qs + (size_t)(b*CCH + h*16) * NSQ + n;
    float p[16];
    float m = -1e30f;
    #pragma unroll
    for (int d = 0; d < 16; d++) { p[d] = qb[(size_t)d * NSQ]; m = fmaxf(m, p[d]); }
    float s = 0.f;
    #pragma unroll
    for (int d = 0; d < 16; d++) { p[d] = expf(p[d] - m); s += p[d]; }
    float inv = 1.f / s;

    int i = n >> 7, j = n & 127;
    #pragma unroll
    for (int e = 0; e < 16; e++) {
        float a = 0.f;
        #pragma unroll
        for (int d = 0; d < 16; d++) a += cs[d][e] * p[d];
        a *= inv;
        // squeezed layout: att_s[b][c][i][j] = att value at x = 2j + (i&1)
        g_att[((size_t)(b*CCH + h*16 + e) * HH + i) * WHF + j] = a;
    }
}

// ---------------- 5x5 conv 64 -> 128, pad 2, checkerboard-sparse input ----------------
// Input is squeezed att: nonzero full-grid position (yy, xx) iff (yy+xx) even,
// value = att_s[yy][(xx - (yy&1))/2]. Only active taps computed (~half the FMAs),
// accumulated pairwise with fma.rn.f32x2 (outputs v and v+2 share taps).
__global__ __launch_bounds__(256) void conv5_kernel(
    const float* __restrict__ wt, const float* __restrict__ bias)
{
    __shared__ float  xs[8][68];     // squeezed rows with halo
    __shared__ float2 wsd[16*25];    // weights duplicated (w,w)
    int X0  = blockIdx.x * 128;
    int y0  = blockIdx.y * 4;
    int b   = blockIdx.z >> 3;
    int cot = blockIdx.z & 7;
    int tid = threadIdx.x;
    int cg  = tid & 3;               // 4 co each -> warp-uniform py below
    int px0 = ((tid >> 2) & 15) * 8; // 0..120
    int py  = tid >> 6;              // 0..3, uniform per warp
    int th  = px0 >> 1;
    int jb  = X0/2 - 1;

    // acc2[u][m]: m=0 -> (v0,v2), m=1 -> (v1,v3), m=2 -> (v4,v6), m=3 -> (v5,v7)
    u64 acc2[4][4];
    #pragma unroll
    for (int u = 0; u < 4; u++)
        #pragma unroll
        for (int m = 0; m < 4; m++) acc2[u][m] = 0ull;

    for (int ci = 0; ci < 64; ci++) {
        __syncthreads();
        const float* ib = g_att + (size_t)(b*CCH + ci) * NSQ;
        for (int q = tid; q < 544; q += 256) {
            int r = q / 68, t = q - r * 68;
            int yy = y0 + r - 2;
            int jj = jb + t;
            float v = 0.f;
            if (yy >= 0 && yy < HH && jj >= 0 && jj < WHF) v = ib[yy*WHF + jj];
            xs[r][t] = v;
        }
        for (int q = tid; q < 400; q += 256) {
            int co = q / 25, tap = q - co * 25;
            float wv = wt[((size_t)(cot*16 + co) * 64 + ci) * 25 + tap];
            wsd[co*25 + tap] = make_float2(wv, wv);
        }
        __syncthreads();

        #pragma unroll
        for (int dy = 0; dy < 5; dy++) {
            int r = py + dy;
            float4 a4 = *reinterpret_cast<const float4*>(&xs[r][th]);
            float4 b4 = *reinterpret_cast<const float4*>(&xs[r][th + 4]);
            float rv[8] = {a4.x,a4.y,a4.z,a4.w, b4.x,b4.y,b4.z,b4.w};
            u64 rp[5];
            #pragma unroll
            for (int t = 0; t < 5; t++) rp[t] = pk(rv[t], rv[t+1]);

            const u64* wrow = reinterpret_cast<const u64*>(wsd) + (cg*4)*25 + dy*5;
            if ((r & 1) == 0) {   // input-row parity 0: taps with (v+dx) even
                #pragma unroll
                for (int u = 0; u < 4; u++) {
                    const u64* wr = wrow + u*25;
                    // v even (pairs base 0,4), dx in {0,2,4}
                    #pragma unroll
                    for (int dx = 0; dx < 5; dx += 2) {
                        u64 w = wr[dx];
                        fma2(acc2[u][0], w, rp[dx>>1]);
                        fma2(acc2[u][2], w, rp[(dx>>1) + 2]);
                    }
                    // v odd (pairs base 1,5), dx in {1,3}
                    #pragma unroll
                    for (int dx = 1; dx < 5; dx += 2) {
                        u64 w = wr[dx];
                        fma2(acc2[u][1], w, rp[(1+dx)>>1]);
                        fma2(acc2[u][3], w, rp[(5+dx)>>1]);
                    }
                }
            } else {              // parity 1: taps with (v+dx) odd
                #pragma unroll
                for (int u = 0; u < 4; u++) {
                    const u64* wr = wrow + u*25;
                    // v even, dx in {1,3}
                    #pragma unroll
                    for (int dx = 1; dx < 5; dx += 2) {
                        u64 w = wr[dx];
                        fma2(acc2[u][0], w, rp[(dx-1)>>1]);
                        fma2(acc2[u][2], w, rp[(dx+3)>>1]);
                    }
                    // v odd, dx in {0,2,4}
                    #pragma unroll
                    for (int dx = 0; dx < 5; dx += 2) {
                        u64 w = wr[dx];
                        fma2(acc2[u][1], w, rp[dx>>1]);
                        fma2(acc2[u][3], w, rp[(dx>>1) + 2]);
                    }
                }
            }
        }
    }

    #pragma unroll
    for (int u = 0; u < 4; u++) {
        int co = cot*16 + cg*4 + u;
        float bb = bias[co];
        float2 q0 = upk(acc2[u][0]);  // v0, v2
        float2 q1 = upk(acc2[u][1]);  // v1, v3
        float2 q2 = upk(acc2[u][2]);  // v4, v6
        float2 q3 = upk(acc2[u][3]);  // v5, v7
        size_t base = ((size_t)(b*C2 + co) * HH + (y0 + py)) * WWD + X0 + px0;
        float4 o0 = make_float4(q0.x + bb, q1.x + bb, q0.y + bb, q1.y + bb);
        float4 o1 = make_float4(q2.x + bb, q3.x + bb, q2.y + bb, q3.y + bb);
        *reinterpret_cast<float4*>(&g_attn[base])     = o0;
        *reinterpret_cast<float4*>(&g_attn[base + 4]) = o1;
    }
}

// ---------------- depthwise 3x3 (256 ch) + gelu ----------------
__global__ void dw_gelu_kernel(const float* __restrict__ in,
                               const float* __restrict__ wt,
                               const float* __restrict__ bias,
                               float* __restrict__ out)
{
    int id = blockIdx.x * blockDim.x + threadIdx.x;
    if (id >= BB*C4*HWW) return;
    int j = id & 255;
    int i = (id >> 8) & 255;
    int c = (id >> 16) & 255;
    int b = id >> 24;
    float w[9];
    #pragma unroll
    for (int t = 0; t < 9; t++) w[t] = __ldg(&wt[c*9 + t]);
    float acc = bias[c];
    const float* base = in + (size_t)(b*C4 + c) * HWW;
    #pragma unroll
    for (int dy = -1; dy <= 1; dy++) {
        int yy = i + dy;
        if (yy < 0 || yy >= HH) continue;
        #pragma unroll
        for (int dx = -1; dx <= 1; dx++) {
            int xx = j + dx;
            if (xx < 0 || xx >= WWD) continue;
            acc += w[(dy+1)*3 + (dx+1)] * base[yy*WWD + xx];
        }
    }
    out[id] = gelu_f(acc);
}

// ---------------- launch ----------------
extern "C" void kernel_launch(void* const* d_in, const int* in_sizes, int n_in,
                              void* d_out, int out_size)
{
    const float* x1   = (const float*)d_in[0];
    const float* x2   = (const float*)d_in[1];
    const float* q1_w = (const float*)d_in[2];
    const float* q1_b = (const float*)d_in[3];
    const float* q2_w = (const float*)d_in[4];
    const float* q2_b = (const float*)d_in[5];
    const float* k1_w = (const float*)d_in[6];
    const float* k1_b = (const float*)d_in[7];
    const float* k2_w = (const float*)d_in[8];
    const float* k2_b = (const float*)d_in[9];
    const float* v1_w = (const float*)d_in[10];
    const float* v1_b = (const float*)d_in[11];
    const float* v2_w = (const float*)d_in[12];
    const float* v2_b = (const float*)d_in[13];
    const float* r_w  = (const float*)d_in[14];
    const float* r_b  = (const float*)d_in[15];
    const float* m1_w = (const float*)d_in[16];
    const float* m1_b = (const float*)d_in[17];
    const float* m2_w = (const float*)d_in[18];
    const float* m2_b = (const float*)d_in[19];
    const float* m3_w = (const float*)d_in[20];
    const float* m3_b = (const float*)d_in[21];
    float* out = (float*)d_out;

    float *p_q1, *p_k1, *p_v1, *p_qs, *p_ks, *p_vs, *p_attn, *p_m1, *p_m2;
    cudaGetSymbolAddress((void**)&p_q1, g_q1);
    cudaGetSymbolAddress((void**)&p_k1, g_k1);
    cudaGetSymbolAddress((void**)&p_v1, g_v1);
    cudaGetSymbolAddress((void**)&p_qs, g_qs);
    cudaGetSymbolAddress((void**)&p_ks, g_ks);
    cudaGetSymbolAddress((void**)&p_vs, g_vs);
    cudaGetSymbolAddress((void**)&p_attn, g_attn);
    cudaGetSymbolAddress((void**)&p_m1, g_m1);
    cudaGetSymbolAddress((void**)&p_m2, g_m2);

    dim3 g1(HWW/128, 1, BB);
    conv1x1_kernel<64,64,0,1><<<g1, 256>>>(x1, q1_w, q1_b, nullptr, p_q1);
    conv1x1_kernel<64,64,0,2><<<g1, 256>>>(x1, k1_w, k1_b, nullptr, p_k1);
    conv1x1_kernel<64,64,0,0><<<g1, 256>>>(x2, v1_w, v1_b, nullptr, p_v1);

    int ndw = BB*CCH*NSQ;
    dw_squeeze_kernel<<<ndw/256, 256>>>(p_q1, q2_w, q2_b, p_qs, 0);
    dw_squeeze_kernel<<<ndw/256, 256>>>(p_k1, k2_w, k2_b, p_ks, 1);
    dw_squeeze_kernel<<<ndw/256, 256>>>(p_v1, v2_w, v2_b, p_vs, 1);

    softmax_k_kernel<<<BB*CCH, 512>>>(p_ks);

    ctx_zero_kernel<<<16, 256>>>();
    ctx_kernel<<<dim3(BB*NHEADS, 32), 256>>>();

    att_kernel<<<dim3(NSQ/256, BB*NHEADS), 256>>>();

    conv5_kernel<<<dim3(2, 64, 32), 256>>>(r_w, r_b);

    conv1x1_kernel<128,256,1,0><<<dim3(HWW/128, 4, BB), 256>>>(p_attn, m1_w, m1_b, nullptr, p_m1);

    dw_gelu_kernel<<<(BB*C4*HWW)/256, 256>>>(p_m1, m2_w, m2_b, p_m2);

    conv1x1_kernel<256,128,2,0><<<dim3(HWW/128, 2, BB), 256>>>(p_m2, m3_w, m3_b, p_attn, out);
}

// round 9
// speedup vs baseline: 1.5888x; 1.5865x over previous
#include <cuda_runtime.h>
#include <cstdint>

#define BB 4
#define CCH 64
#define HH 256
#define WWD 256
#define HWW (HH*WWD)
#define NHEADS 4
#define DDIM 16
#define WHF 128
#define NSQ (HH*WHF)
#define C2 128
#define C4 256

typedef unsigned long long u64;
typedef uint32_t u32;

// ---------------- scratch ----------------
__device__ float g_q1[BB*CCH*HWW];
__device__ float g_k1[BB*CCH*HWW];
__device__ float g_v1[BB*CCH*HWW];
__device__ float g_qs[BB*CCH*NSQ];
__device__ float g_ks[BB*CCH*NSQ];
__device__ float g_vs[BB*CCH*NSQ];
__device__ float g_ctx[BB*NHEADS*DDIM*DDIM];
__device__ float g_att[(size_t)BB*NSQ*CCH];   // squeezed NHWC: [b][r][u][ci]
__device__ float g_attn[(size_t)BB*C2*HWW];   // NCHW attention (conv5 out)
__device__ float g_m1[(size_t)BB*C4*HWW];     // NCHW
__device__ float g_m2[(size_t)BB*C4*HWW];     // NCHW
__device__ float g_w5[25*128*64];             // [tap][co][ci], tf32-rounded

__device__ __forceinline__ float gelu_f(float x) {
    return 0.5f * x * (1.0f + erff(x * 0.7071067811865476f));
}
__device__ __forceinline__ float rna(float x) {
    u32 u; asm("cvt.rna.tf32.f32 %0, %1;" : "=r"(u) : "f"(x));
    return __uint_as_float(u);
}
__device__ __forceinline__ float4 rna4(float4 v) {
    v.x=rna(v.x); v.y=rna(v.y); v.z=rna(v.z); v.w=rna(v.w); return v;
}
__device__ __forceinline__ void fma2(u64& d, u64 a, u64 b) {
    asm("fma.rn.f32x2 %0, %1, %2, %0;" : "+l"(d) : "l"(a), "l"(b));
}
__device__ __forceinline__ float2 upk(u64 v) {
    u32 a, b;
    asm("mov.b64 {%0, %1}, %2;" : "=r"(a), "=r"(b) : "l"(v));
    return make_float2(__uint_as_float(a), __uint_as_float(b));
}
// tf32 warp MMA: D(16x8) += A(16x8,row) * B(8x8,col)
__device__ __forceinline__ void mma8(float* d, const u32* a, const u32* b) {
    asm volatile(
        "mma.sync.aligned.m16n8k8.row.col.f32.tf32.tf32.f32 "
        "{%0,%1,%2,%3}, {%4,%5,%6,%7}, {%8,%9}, {%0,%1,%2,%3};"
        : "+f"(d[0]), "+f"(d[1]), "+f"(d[2]), "+f"(d[3])
        : "r"(a[0]), "r"(a[1]), "r"(a[2]), "r"(a[3]), "r"(b[0]), "r"(b[1]));
}

// ---------------- prep: conv5 weights -> [tap][co][ci], rna ----------------
__global__ void prep_w5(const float* __restrict__ w) {
    int id = blockIdx.x * 256 + threadIdx.x;
    if (id >= 25*128*64) return;
    int ci = id & 63, co = (id >> 6) & 127, t = id >> 13;
    g_w5[(t*128 + co)*64 + ci] = rna(w[(co*64 + ci)*25 + t]);
}

// ---------------- 1x1 conv (qkv), fp32 f32x2 ----------------
template<int CIN, int COUT, int MASK>
__global__ __launch_bounds__(256) void conv1x1_kernel(
    const float* __restrict__ in, const float* __restrict__ wt,
    const float* __restrict__ bias, float* __restrict__ out)
{
    __shared__ float2 Wsd[32*64];
    __shared__ float  Xs[32][128];
    const int p0  = blockIdx.x * 128;
    const int b   = blockIdx.z;
    const int tid = threadIdx.x;
    const int px0 = (tid & 15) * 4;
    const int co0 = (tid >> 4) * 4;

    u64 acc2[4][4];
    #pragma unroll
    for (int u = 0; u < 4; u++)
        #pragma unroll
        for (int v = 0; v < 4; v++) acc2[u][v] = 0ull;

    for (int k0 = 0; k0 < CIN; k0 += 32) {
        __syncthreads();
        #pragma unroll
        for (int q = tid; q < 2048; q += 256) {
            int co = q & 63, ci = q >> 6;
            float wv = wt[(size_t)co * CIN + k0 + ci];
            Wsd[ci*64 + co] = make_float2(wv, wv);
        }
        #pragma unroll
        for (int q = tid; q < 1024; q += 256) {
            int ci = q >> 5, f4 = q & 31;
            int p  = p0 + f4 * 4;
            float4 v = *reinterpret_cast<const float4*>(
                in + (size_t)(b * CIN + k0 + ci) * HWW + p);
            if (MASK) {
                int pb = ((p >> 8) + (p & 255)) & 1;
                int kp = (MASK == 1) ? pb : (pb ^ 1);
                if (kp == 0) { v.y = 0.f; v.w = 0.f; }
                else         { v.x = 0.f; v.z = 0.f; }
            }
            *reinterpret_cast<float4*>(&Xs[ci][f4*4]) = v;
        }
        __syncthreads();
        #pragma unroll
        for (int k = 0; k < 32; k++) {
            u64 xp0 = *reinterpret_cast<const u64*>(&Xs[k][px0]);
            u64 xp1 = *reinterpret_cast<const u64*>(&Xs[k][px0 + 2]);
            u64 xp2 = *reinterpret_cast<const u64*>(&Xs[k][px0 + 64]);
            u64 xp3 = *reinterpret_cast<const u64*>(&Xs[k][px0 + 66]);
            #pragma unroll
            for (int u = 0; u < 4; u++) {
                u64 wd = *reinterpret_cast<const u64*>(&Wsd[k*64 + co0 + u]);
                fma2(acc2[u][0], wd, xp0);
                fma2(acc2[u][1], wd, xp1);
                fma2(acc2[u][2], wd, xp2);
                fma2(acc2[u][3], wd, xp3);
            }
        }
    }
    #pragma unroll
    for (int u = 0; u < 4; u++) {
        int co = co0 + u;
        float bb = bias[co];
        size_t base = (size_t)(b * COUT + co) * HWW + p0;
        #pragma unroll
        for (int g = 0; g < 2; g++) {
            float2 pa = upk(acc2[u][g*2 + 0]);
            float2 pb = upk(acc2[u][g*2 + 1]);
            *reinterpret_cast<float4*>(out + base + px0 + g*64) =
                make_float4(pa.x + bb, pa.y + bb, pb.x + bb, pb.y + bb);
        }
    }
}

// ---------------- depthwise 3x3 + checkerboard squeeze ----------------
__global__ void dw_squeeze_kernel(const float* __restrict__ in,
                                  const float* __restrict__ wt,
                                  const float* __restrict__ bias,
                                  float* __restrict__ out, int anchor)
{
    int id = blockIdx.x * blockDim.x + threadIdx.x;
    if (id >= BB*CCH*NSQ) return;
    int j = id & (WHF-1);
    int i = (id >> 7) & (HH-1);
    int c = (id >> 15) & (CCH-1);
    int b = id >> 21;
    int x = 2*j + (anchor ? (1 - (i & 1)) : (i & 1));
    float w[9];
    #pragma unroll
    for (int t = 0; t < 9; t++) w[t] = __ldg(&wt[c*9 + t]);
    float acc = bias[c];
    const float* base = in + (size_t)(b*CCH + c) * HWW;
    #pragma unroll
    for (int dy = -1; dy <= 1; dy++) {
        int yy = i + dy;
        if (yy < 0 || yy >= HH) continue;
        #pragma unroll
        for (int dx = -1; dx <= 1; dx++) {
            int xx = x + dx;
            if (xx < 0 || xx >= WWD) continue;
            acc += w[(dy+1)*3 + (dx+1)] * base[yy*WWD + xx];
        }
    }
    out[id] = acc;
}

// ---------------- softmax over n per (b,c) row ----------------
__global__ __launch_bounds__(512) void softmax_k_kernel(float* __restrict__ data)
{
    __shared__ float sm[16];
    float* ptr = data + (size_t)blockIdx.x * NSQ;
    int tid = threadIdx.x;
    float m = -1e30f;
    for (int idx = tid; idx < NSQ; idx += 512) m = fmaxf(m, ptr[idx]);
    #pragma unroll
    for (int o = 16; o; o >>= 1) m = fmaxf(m, __shfl_xor_sync(0xffffffffu, m, o));
    if ((tid & 31) == 0) sm[tid >> 5] = m;
    __syncthreads();
    if (tid < 32) {
        float t = (tid < 16) ? sm[tid] : -1e30f;
        #pragma unroll
        for (int o = 8; o; o >>= 1) t = fmaxf(t, __shfl_xor_sync(0xffffffffu, t, o));
        if (tid == 0) sm[0] = t;
    }
    __syncthreads();
    m = sm[0];
    __syncthreads();
    float s = 0.f;
    for (int idx = tid; idx < NSQ; idx += 512) s += expf(ptr[idx] - m);
    #pragma unroll
    for (int o = 16; o; o >>= 1) s += __shfl_xor_sync(0xffffffffu, s, o);
    if ((tid & 31) == 0) sm[tid >> 5] = s;
    __syncthreads();
    if (tid < 32) {
        float t = (tid < 16) ? sm[tid] : 0.f;
        #pragma unroll
        for (int o = 8; o; o >>= 1) t += __shfl_xor_sync(0xffffffffu, t, o);
        if (tid == 0) sm[0] = t;
    }
    __syncthreads();
    float inv = 1.f / sm[0];
    for (int idx = tid; idx < NSQ; idx += 512) ptr[idx] = expf(ptr[idx] - m) * inv;
}

// ---------------- ctx ----------------
__global__ void ctx_zero_kernel() {
    int id = blockIdx.x * blockDim.x + threadIdx.x;
    if (id < BB*NHEADS*DDIM*DDIM) g_ctx[id] = 0.f;
}
__global__ __launch_bounds__(256) void ctx_kernel()
{
    __shared__ float ka[16][129];
    __shared__ float va[16][129];
    int bh = blockIdx.x, chunk = blockIdx.y;
    int b = bh >> 2, h = bh & 3;
    int tid = threadIdx.x;
    int d = tid >> 4, e = tid & 15;
    const float* kbase = g_ks + (size_t)(b*CCH + h*16) * NSQ;
    const float* vbase = g_vs + (size_t)(b*CCH + h*16) * NSQ;
    float acc = 0.f;
    for (int sub = 0; sub < 8; sub++) {
        int n0 = chunk * 1024 + sub * 128;
        __syncthreads();
        #pragma unroll
        for (int q = tid; q < 2048; q += 256) {
            int r = q >> 7, t = q & 127;
            ka[r][t] = kbase[(size_t)r * NSQ + n0 + t];
            va[r][t] = vbase[(size_t)r * NSQ + n0 + t];
        }
        __syncthreads();
        #pragma unroll
        for (int t = 0; t < 128; t++) acc += ka[d][t] * va[e][t];
    }
    atomicAdd(&g_ctx[bh*256 + tid], acc);
}

// ---------------- q softmax(d) + ctx -> squeezed NHWC att ----------------
__global__ __launch_bounds__(256) void att_kernel()
{
    __shared__ float cs[16][17];
    int bh = blockIdx.y;
    int b = bh >> 2, h = bh & 3;
    int tid = threadIdx.x;
    int n = blockIdx.x * 256 + tid;
    cs[tid >> 4][tid & 15] = g_ctx[bh*256 + tid];
    __syncthreads();
    const float* qb = g_qs + (size_t)(b*CCH + h*16) * NSQ + n;
    float p[16];
    float m = -1e30f;
    #pragma unroll
    for (int d = 0; d < 16; d++) { p[d] = qb[(size_t)d * NSQ]; m = fmaxf(m, p[d]); }
    float s = 0.f;
    #pragma unroll
    for (int d = 0; d < 16; d++) { p[d] = expf(p[d] - m); s += p[d]; }
    float inv = 1.f / s;
    float va[16];
    #pragma unroll
    for (int e = 0; e < 16; e++) {
        float a = 0.f;
        #pragma unroll
        for (int d = 0; d < 16; d++) a += cs[d][e] * p[d];
        va[e] = a * inv;
    }
    // squeezed NHWC: S[b][i][j][c], value lives at full-grid x = 2j + (i&1)
    float* pa = g_att + ((size_t)n + (size_t)b*NSQ) * CCH + h*16;
    #pragma unroll
    for (int g = 0; g < 4; g++)
        *reinterpret_cast<float4*>(pa + g*4) =
            make_float4(va[g*4], va[g*4+1], va[g*4+2], va[g*4+3]);
}

// ---------------- conv5 via warp-MMA (parity-split tap GEMMs) ----------------
// grid (y=256, ch=2, b=4), 256 thr. smem: S5 [5][130][68] | A [64][68]
#define C5_S   0
#define C5_A   (5*130*68*4)
#define C5_TOT (C5_A + 64*68*4)

__global__ __launch_bounds__(256) void conv5_mma(const float* __restrict__ bias)
{
    extern __shared__ float sm[];
    float* S5 = sm;                       // [r5][u'][ci] pad 68
    float* As = sm + 5*130*68;            // [co][ci] pad 68
    int tid = threadIdx.x;
    int warp = tid >> 5, lane = tid & 31;
    int gid = lane >> 2, tig = lane & 3;
    int mw = warp & 1, nw = warp >> 1;    // M: 2x32, N: 4x32
    int y = blockIdx.x, ch = blockIdx.y, b = blockIdx.z;

    // stage 5 squeezed rows, u' = u+1 (halo), zero padded
    for (int q = tid; q < 5*130*16; q += 256) {
        int r5 = q / (130*16), rem = q % (130*16);
        int up = rem >> 4, cig = rem & 15;
        int r = y + r5 - 2, u = up - 1;
        float4 v = make_float4(0.f, 0.f, 0.f, 0.f);
        if (r >= 0 && r < HH && u >= 0 && u < WHF)
            v = rna4(*reinterpret_cast<const float4*>(
                g_att + ((size_t)b*NSQ + r*WHF + u) * CCH + cig*4));
        *reinterpret_cast<float4*>(&S5[(r5*130 + up)*68 + cig*4]) = v;
    }

    float acc[2][2][4][4];   // [parity][mt][nt][frag]
    #pragma unroll
    for (int t = 0; t < 2; t++)
        #pragma unroll
        for (int mt = 0; mt < 2; mt++)
            #pragma unroll
            for (int nt = 0; nt < 4; nt++)
                #pragma unroll
                for (int f = 0; f < 4; f++) acc[t][mt][nt][f] = 0.f;

    for (int dy = 0; dy < 5; dy++) {
        int r = y + dy - 2;
        if (r < 0 || r >= HH) continue;
        int rp = r & 1;
        for (int dx = 0; dx < 5; dx++) {
            int t   = (r + dx) & 1;
            int off = (dx & 1) ? (rp ? (dx-3)/2 : (dx-1)/2) : (dx-2)/2;
            __syncthreads();
            // stage A tile [64 co][64 ci] for this tap, co range ch*64..
            for (int q = tid; q < 1024; q += 256) {
                int co = q >> 4, cig = q & 15;
                *reinterpret_cast<float4*>(&As[co*68 + cig*4]) =
                    *reinterpret_cast<const float4*>(
                        g_w5 + ((dy*5 + dx)*128 + ch*64 + co)*64 + cig*4);
            }
            __syncthreads();
            const float* Brow = &S5[dy*130*68 + (off + 1)*68];
            #pragma unroll
            for (int ks = 0; ks < 8; ks++) {
                int k = ks*8 + tig;
                u32 a[2][4];
                #pragma unroll
                for (int mt = 0; mt < 2; mt++) {
                    int m = mw*32 + mt*16 + gid;
                    a[mt][0] = __float_as_uint(As[m*68 + k]);
                    a[mt][1] = __float_as_uint(As[(m+8)*68 + k]);
                    a[mt][2] = __float_as_uint(As[m*68 + k + 4]);
                    a[mt][3] = __float_as_uint(As[(m+8)*68 + k + 4]);
                }
                #pragma unroll
                for (int nt = 0; nt < 4; nt++) {
                    int n = nw*32 + nt*8 + gid;
                    u32 bf[2];
                    bf[0] = __float_as_uint(Brow[n*68 + k]);
                    bf[1] = __float_as_uint(Brow[n*68 + k + 4]);
                    mma8(acc[t][0][nt], a[0], bf);
                    mma8(acc[t][1][nt], a[1], bf);
                }
            }
        }
    }

    // epilogue: O[co][2w+t] = acc + bias, NCHW
    #pragma unroll
    for (int mt = 0; mt < 2; mt++) {
        int co = ch*64 + mw*32 + mt*16 + gid;
        float b0 = bias[co], b8 = bias[co + 8];
        float* r0 = g_attn + ((size_t)(b*C2 + co)     * HH + y) * WWD;
        float* r8 = g_attn + ((size_t)(b*C2 + co + 8) * HH + y) * WWD;
        #pragma unroll
        for (int t = 0; t < 2; t++)
            #pragma unroll
            for (int nt = 0; nt < 4; nt++) {
                int w = nw*32 + nt*8 + 2*tig;
                int x = 2*w + t;
                float* a = acc[t][mt][nt];
                r0[x]     = a[0] + b0;
                r0[x + 2] = a[1] + b0;
                r8[x]     = a[2] + b8;
                r8[x + 2] = a[3] + b8;
            }
    }
}

// ---------------- generic 1x1 MMA GEMM: M=128 co x N=128 px, K=KK ----------------
// smem: A [128][132] | B [128][132] (per K-chunk of 128)
#define MM_TOT (2*128*132*4)

template<int KK, int ACT>   // ACT: 1 gelu -> g_m1 ; 2 bias+residual -> out
__global__ __launch_bounds__(256) void mlp_mma(
    const float* __restrict__ inp,   // NCHW [b][KK(+base)][p]
    const float* __restrict__ wt,    // [co][KTOT] row-major
    const float* __restrict__ bias,
    float* __restrict__ outp,        // NCHW dest
    int co_base, int ktot)
{
    extern __shared__ float sm[];
    float* As = sm;             // [co][ci] pad 132
    float* Bs = sm + 128*132;   // [ci][px] pad 132
    int tid = threadIdx.x;
    int warp = tid >> 5, lane = tid & 31;
    int gid = lane >> 2, tig = lane & 3;
    int mw = warp & 3, nw = warp >> 2;   // M: 4x32, N: 2x64
    int P0 = blockIdx.x * 128, b = blockIdx.z;

    float acc[2][8][4];
    #pragma unroll
    for (int mt = 0; mt < 2; mt++)
        #pragma unroll
        for (int nt = 0; nt < 8; nt++)
            #pragma unroll
            for (int f = 0; f < 4; f++) acc[mt][nt][f] = 0.f;

    for (int kc = 0; kc < KK/128; kc++) {
        if (kc) __syncthreads();
        for (int q = tid; q < 128*32; q += 256) {
            int co = q >> 5, cig = q & 31;
            *reinterpret_cast<float4*>(&As[co*132 + cig*4]) =
                rna4(*reinterpret_cast<const float4*>(
                    wt + (size_t)(co_base + co) * ktot + kc*128 + cig*4));
        }
        for (int q = tid; q < 128*32; q += 256) {
            int ci = q >> 5, pg = q & 31;
            *reinterpret_cast<float4*>(&Bs[ci*132 + pg*4]) =
                rna4(*reinterpret_cast<const float4*>(
                    inp + (size_t)(b*KK + kc*128 + ci) * HWW + P0 + pg*4));
        }
        __syncthreads();
        #pragma unroll
        for (int ks = 0; ks < 16; ks++) {
            int k = ks*8 + tig;
            u32 a[2][4];
            #pragma unroll
            for (int mt = 0; mt < 2; mt++) {
                int m = mw*32 + mt*16 + gid;
                a[mt][0] = __float_as_uint(As[m*132 + k]);
                a[mt][1] = __float_as_uint(As[(m+8)*132 + k]);
                a[mt][2] = __float_as_uint(As[m*132 + k + 4]);
                a[mt][3] = __float_as_uint(As[(m+8)*132 + k + 4]);
            }
            #pragma unroll
            for (int nt = 0; nt < 8; nt++) {
                int n = nw*64 + nt*8 + gid;
                u32 bf[2];
                bf[0] = __float_as_uint(Bs[k*132 + n]);
                bf[1] = __float_as_uint(Bs[(k+4)*132 + n]);
                mma8(acc[0][nt], a[0], bf);
                mma8(acc[1][nt], a[1], bf);
            }
        }
    }

    int cout_tot = (ACT == 1) ? C4 : C2;
    #pragma unroll
    for (int mt = 0; mt < 2; mt++) {
        int col = mw*32 + mt*16 + gid;
        int co = co_base + col;
        float b0 = bias[co], b8 = bias[co + 8];
        float* o0 = outp + (size_t)(b*cout_tot + co)     * HWW + P0;
        float* o8 = outp + (size_t)(b*cout_tot + co + 8) * HWW + P0;
        const float* r0 = g_attn + (size_t)(b*C2 + col)     * HWW + P0;
        const float* r8 = g_attn + (size_t)(b*C2 + col + 8) * HWW + P0;
        #pragma unroll
        for (int nt = 0; nt < 8; nt++) {
            int px = nw*64 + nt*8 + 2*tig;
            float* a = acc[mt][nt];
            if (ACT == 1) {
                *reinterpret_cast<float2*>(o0 + px) =
                    make_float2(gelu_f(a[0] + b0), gelu_f(a[1] + b0));
                *reinterpret_cast<float2*>(o8 + px) =
                    make_float2(gelu_f(a[2] + b8), gelu_f(a[3] + b8));
            } else {
                float2 v0 = *reinterpret_cast<const float2*>(r0 + px);
                float2 v8 = *reinterpret_cast<const float2*>(r8 + px);
                *reinterpret_cast<float2*>(o0 + px) =
                    make_float2(a[0] + b0 + v0.x, a[1] + b0 + v0.y);
                *reinterpret_cast<float2*>(o8 + px) =
                    make_float2(a[2] + b8 + v8.x, a[3] + b8 + v8.y);
            }
        }
    }
}

// ---------------- depthwise 3x3 (256 ch) + gelu, NCHW ----------------
__global__ void dw_gelu_kernel(const float* __restrict__ in,
                               const float* __restrict__ wt,
                               const float* __restrict__ bias,
                               float* __restrict__ out)
{
    int id = blockIdx.x * blockDim.x + threadIdx.x;
    if (id >= BB*C4*HWW) return;
    int j = id & 255;
    int i = (id >> 8) & 255;
    int c = (id >> 16) & 255;
    int b = id >> 24;
    float w[9];
    #pragma unroll
    for (int t = 0; t < 9; t++) w[t] = __ldg(&wt[c*9 + t]);
    float acc = bias[c];
    const float* base = in + (size_t)(b*C4 + c) * HWW;
    #pragma unroll
    for (int dy = -1; dy <= 1; dy++) {
        int yy = i + dy;
        if (yy < 0 || yy >= HH) continue;
        #pragma unroll
        for (int dx = -1; dx <= 1; dx++) {
            int xx = j + dx;
            if (xx < 0 || xx >= WWD) continue;
            acc += w[(dy+1)*3 + (dx+1)] * base[yy*WWD + xx];
        }
    }
    out[id] = gelu_f(acc);
}

// ---------------- launch ----------------
extern "C" void kernel_launch(void* const* d_in, const int* in_sizes, int n_in,
                              void* d_out, int out_size)
{
    const float* x1   = (const float*)d_in[0];
    const float* x2   = (const float*)d_in[1];
    const float* q1_w = (const float*)d_in[2];
    const float* q1_b = (const float*)d_in[3];
    const float* q2_w = (const float*)d_in[4];
    const float* q2_b = (const float*)d_in[5];
    const float* k1_w = (const float*)d_in[6];
    const float* k1_b = (const float*)d_in[7];
    const float* k2_w = (const float*)d_in[8];
    const float* k2_b = (const float*)d_in[9];
    const float* v1_w = (const float*)d_in[10];
    const float* v1_b = (const float*)d_in[11];
    const float* v2_w = (const float*)d_in[12];
    const float* v2_b = (const float*)d_in[13];
    const float* r_w  = (const float*)d_in[14];
    const float* r_b  = (const float*)d_in[15];
    const float* m1_w = (const float*)d_in[16];
    const float* m1_b = (const float*)d_in[17];
    const float* m2_w = (const float*)d_in[18];
    const float* m2_b = (const float*)d_in[19];
    const float* m3_w = (const float*)d_in[20];
    const float* m3_b = (const float*)d_in[21];
    float* out = (float*)d_out;

    float *p_q1, *p_k1, *p_v1, *p_qs, *p_ks, *p_vs, *p_attn, *p_m1, *p_m2;
    cudaGetSymbolAddress((void**)&p_q1, g_q1);
    cudaGetSymbolAddress((void**)&p_k1, g_k1);
    cudaGetSymbolAddress((void**)&p_v1, g_v1);
    cudaGetSymbolAddress((void**)&p_qs, g_qs);
    cudaGetSymbolAddress((void**)&p_ks, g_ks);
    cudaGetSymbolAddress((void**)&p_vs, g_vs);
    cudaGetSymbolAddress((void**)&p_attn, g_attn);
    cudaGetSymbolAddress((void**)&p_m1, g_m1);
    cudaGetSymbolAddress((void**)&p_m2, g_m2);

    cudaFuncSetAttribute(conv5_mma, cudaFuncAttributeMaxDynamicSharedMemorySize, C5_TOT);
    cudaFuncSetAttribute(mlp_mma<128,1>, cudaFuncAttributeMaxDynamicSharedMemorySize, MM_TOT);
    cudaFuncSetAttribute(mlp_mma<256,2>, cudaFuncAttributeMaxDynamicSharedMemorySize, MM_TOT);

    prep_w5<<<800, 256>>>(r_w);

    dim3 g1(HWW/128, 1, BB);
    conv1x1_kernel<64,64,1><<<g1, 256>>>(x1, q1_w, q1_b, p_q1);
    conv1x1_kernel<64,64,2><<<g1, 256>>>(x1, k1_w, k1_b, p_k1);
    conv1x1_kernel<64,64,0><<<g1, 256>>>(x2, v1_w, v1_b, p_v1);

    int ndw = BB*CCH*NSQ;
    dw_squeeze_kernel<<<ndw/256, 256>>>(p_q1, q2_w, q2_b, p_qs, 0);
    dw_squeeze_kernel<<<ndw/256, 256>>>(p_k1, k2_w, k2_b, p_ks, 1);
    dw_squeeze_kernel<<<ndw/256, 256>>>(p_v1, v2_w, v2_b, p_vs, 1);

    softmax_k_kernel<<<BB*CCH, 512>>>(p_ks);
    ctx_zero_kernel<<<16, 256>>>();
    ctx_kernel<<<dim3(BB*NHEADS, 32), 256>>>();
    att_kernel<<<dim3(NSQ/256, BB*NHEADS), 256>>>();

    conv5_mma<<<dim3(HH, 2, BB), 256, C5_TOT>>>(r_b);

    // m1: 128 -> 256 (two co halves), gelu
    mlp_mma<128,1><<<dim3(HWW/128, 1, BB), 256, MM_TOT>>>(p_attn, m1_w, m1_b, p_m1, 0,   128);
    mlp_mma<128,1><<<dim3(HWW/128, 1, BB), 256, MM_TOT>>>(p_attn, m1_w, m1_b, p_m1, 128, 128);

    dw_gelu_kernel<<<(BB*C4*HWW)/256, 256>>>(p_m1, m2_w, m2_b, p_m2);

    // m3: 256 -> 128, bias + residual -> out
    mlp_mma<256,2><<<dim3(HWW/128, 1, BB), 256, MM_TOT>>>(p_m2, m3_w, m3_b, out, 0, 256);
}

// round 13
// speedup vs baseline: 1.6030x; 1.0089x over previous
#include <cuda_runtime.h>
#include <cstdint>

#define BB 4
#define CCH 64
#define HH 256
#define WWD 256
#define HWW (HH*WWD)
#define NHEADS 4
#define WHF 128
#define NSQ (HH*WHF)
#define C2 128
#define C4 256

typedef uint32_t u32;

__device__ float g_q1[BB*CCH*HWW];
__device__ float g_k1[BB*CCH*HWW];
__device__ float g_v1[BB*CCH*HWW];
__device__ float g_qs[BB*CCH*NSQ];
__device__ float g_ks[BB*CCH*NSQ];
__device__ float g_vs[BB*CCH*NSQ];
__device__ float g_ctx[BB*NHEADS*256];
__device__ float g_att[(size_t)BB*NSQ*CCH];   // squeezed NHWC
__device__ float g_attn[(size_t)BB*C2*HWW];   // NCHW
__device__ float g_m1[(size_t)BB*C4*HWW];
__device__ float g_m2[(size_t)BB*C4*HWW];
__device__ float g_w5[25*128*64];
__device__ float g_wq[4096], g_wk[4096], g_wv[4096];
__device__ float g_wm1[C4*C2], g_wm3[C2*C4];

__device__ __forceinline__ float gelu_f(float x) {
    return 0.5f * x * (1.0f + erff(x * 0.7071067811865476f));
}
__device__ __forceinline__ float rna(float x) {
    u32 u; asm("cvt.rna.tf32.f32 %0, %1;" : "=r"(u) : "f"(x));
    return __uint_as_float(u);
}
__device__ __forceinline__ float4 rna4(float4 v) {
    v.x=rna(v.x); v.y=rna(v.y); v.z=rna(v.z); v.w=rna(v.w); return v;
}
__device__ __forceinline__ void mma8(float* d, const u32* a, const u32* b) {
    asm volatile(
        "mma.sync.aligned.m16n8k8.row.col.f32.tf32.tf32.f32 "
        "{%0,%1,%2,%3}, {%4,%5,%6,%7}, {%8,%9}, {%0,%1,%2,%3};"
        : "+f"(d[0]), "+f"(d[1]), "+f"(d[2]), "+f"(d[3])
        : "r"(a[0]), "r"(a[1]), "r"(a[2]), "r"(a[3]), "r"(b[0]), "r"(b[1]));
}

// ---------------- weight prep ----------------
__global__ void prep_w5(const float* __restrict__ w) {
    int id = blockIdx.x * 256 + threadIdx.x;
    if (id >= 25*128*64) return;
    int ci = id & 63, co = (id >> 6) & 127, t = id >> 13;
    g_w5[(t*128 + co)*64 + ci] = rna(w[(co*64 + ci)*25 + t]);
}
__global__ void prep_rna(const float* __restrict__ s, float* __restrict__ d, int n) {
    int id = blockIdx.x * 256 + threadIdx.x;
    if (id < n) d[id] = rna(s[id]);
}

// ---------------- qkv 1x1 conv via MMA: M=64, K=64, N=128 px ----------------
// KEEP: 0 none, 1 keep (i+j)%2==0 (q), 2 keep ==1 (k)
template<int KEEP>
__global__ __launch_bounds__(256) void qkv_mma(
    const float* __restrict__ inp, const float* __restrict__ wpre,
    const float* __restrict__ bias, float* __restrict__ out)
{
    __shared__ float Bs[64*132];
    int tid = threadIdx.x, warp = tid >> 5, lane = tid & 31;
    int gid = lane >> 2, tig = lane & 3;
    int mw = warp & 1, nw = warp >> 1;
    int P0 = blockIdx.x * 128, b = blockIdx.z;
    int want = (KEEP == 2) ? 1 : 0;

    for (int q = tid; q < 64*32; q += 256) {
        int ci = q >> 5, pg = q & 31;
        int p = P0 + pg*4;
        float4 v = rna4(*reinterpret_cast<const float4*>(
            inp + (size_t)(b*64 + ci) * HWW + p));
        if (KEEP) {
            int pb0 = ((p >> 8) + (p & 255)) & 1;
            if (pb0 == want) { v.y = 0.f; v.w = 0.f; }
            else             { v.x = 0.f; v.z = 0.f; }
        }
        *reinterpret_cast<float4*>(&Bs[ci*132 + pg*4]) = v;
    }
    __syncthreads();

    float acc[2][4][4];
    #pragma unroll
    for (int mt = 0; mt < 2; mt++)
        #pragma unroll
        for (int nt = 0; nt < 4; nt++)
            #pragma unroll
            for (int f = 0; f < 4; f++) acc[mt][nt][f] = 0.f;

    #pragma unroll
    for (int ks = 0; ks < 8; ks++) {
        int k = ks*8 + tig;
        u32 a[2][4];
        #pragma unroll
        for (int mt = 0; mt < 2; mt++) {
            int m = mw*32 + mt*16 + gid;
            a[mt][0] = __float_as_uint(__ldg(wpre + m*64 + k));
            a[mt][1] = __float_as_uint(__ldg(wpre + (m+8)*64 + k));
            a[mt][2] = __float_as_uint(__ldg(wpre + m*64 + k + 4));
            a[mt][3] = __float_as_uint(__ldg(wpre + (m+8)*64 + k + 4));
        }
        #pragma unroll
        for (int nt = 0; nt < 4; nt++) {
            int n = nw*32 + nt*8 + gid;
            u32 bf[2];
            bf[0] = __float_as_uint(Bs[k*132 + n]);
            bf[1] = __float_as_uint(Bs[(k+4)*132 + n]);
            mma8(acc[0][nt], a[0], bf);
            mma8(acc[1][nt], a[1], bf);
        }
    }
    #pragma unroll
    for (int mt = 0; mt < 2; mt++) {
        int co = mw*32 + mt*16 + gid;
        float b0 = bias[co], b8 = bias[co + 8];
        float* o0 = out + (size_t)(b*64 + co)     * HWW + P0;
        float* o8 = out + (size_t)(b*64 + co + 8) * HWW + P0;
        #pragma unroll
        for (int nt = 0; nt < 4; nt++) {
            int px = nw*32 + nt*8 + 2*tig;
            float* a = acc[mt][nt];
            *reinterpret_cast<float2*>(o0 + px) = make_float2(a[0] + b0, a[1] + b0);
            *reinterpret_cast<float2*>(o8 + px) = make_float2(a[2] + b8, a[3] + b8);
        }
    }
}

// ---------------- depthwise 3x3 + ckbd squeeze, 4 outputs/thread ----------------
__global__ void dw_squeeze_kernel(const float* __restrict__ in,
                                  const float* __restrict__ wt,
                                  const float* __restrict__ bias,
                                  float* __restrict__ out, int anchor)
{
    int id = blockIdx.x * blockDim.x + threadIdx.x;
    if (id >= BB*CCH*HH*32) return;
    int j4 = id & 31;
    int i  = (id >> 5) & 255;
    int c  = (id >> 13) & 63;
    int b  = id >> 19;
    int j0 = j4 * 4;
    int par = anchor ? (1 - (i & 1)) : (i & 1);
    int xb = 2*j0 + par;
    float w[9];
    #pragma unroll
    for (int t = 0; t < 9; t++) w[t] = __ldg(&wt[c*9 + t]);
    const float* base = in + (size_t)(b*CCH + c) * HWW;

    float row[3][9];
    bool fast = (xb >= 1) && (xb + 7 <= 255);
    #pragma unroll
    for (int dy = 0; dy < 3; dy++) {
        int yy = i + dy - 1;
        if (yy < 0 || yy >= HH) {
            #pragma unroll
            for (int s = 0; s < 9; s++) row[dy][s] = 0.f;
        } else {
            const float* rp = base + yy*WWD;
            if (fast) {
                #pragma unroll
                for (int s = 0; s < 9; s++) row[dy][s] = __ldg(rp + xb - 1 + s);
            } else {
                #pragma unroll
                for (int s = 0; s < 9; s++) {
                    int xx = xb - 1 + s;
                    row[dy][s] = (xx >= 0 && xx < WWD) ? __ldg(rp + xx) : 0.f;
                }
            }
        }
    }
    float bb = bias[c];
    float4 o;
    float* ov = reinterpret_cast<float*>(&o);
    #pragma unroll
    for (int s = 0; s < 4; s++) {
        float acc = bb;
        #pragma unroll
        for (int dy = 0; dy < 3; dy++)
            #pragma unroll
            for (int dx = 0; dx < 3; dx++)
                acc += w[dy*3 + dx] * row[dy][2*s + dx];
        ov[s] = acc;
    }
    *reinterpret_cast<float4*>(out + (size_t)(b*CCH + c) * NSQ + i*WHF + j0) = o;
}

// ---------------- softmax over n per (b,c) row ----------------
__global__ __launch_bounds__(512) void softmax_k_kernel(float* __restrict__ data)
{
    __shared__ float sm[16];
    float* ptr = data + (size_t)blockIdx.x * NSQ;
    int tid = threadIdx.x;
    float m = -1e30f;
    for (int idx = tid; idx < NSQ; idx += 512) m = fmaxf(m, ptr[idx]);
    #pragma unroll
    for (int o = 16; o; o >>= 1) m = fmaxf(m, __shfl_xor_sync(0xffffffffu, m, o));
    if ((tid & 31) == 0) sm[tid >> 5] = m;
    __syncthreads();
    if (tid < 32) {
        float t = (tid < 16) ? sm[tid] : -1e30f;
        #pragma unroll
        for (int o = 8; o; o >>= 1) t = fmaxf(t, __shfl_xor_sync(0xffffffffu, t, o));
        if (tid == 0) sm[0] = t;
    }
    __syncthreads();
    m = sm[0];
    __syncthreads();
    float s = 0.f;
    for (int idx = tid; idx < NSQ; idx += 512) s += expf(ptr[idx] - m);
    #pragma unroll
    for (int o = 16; o; o >>= 1) s += __shfl_xor_sync(0xffffffffu, s, o);
    if ((tid & 31) == 0) sm[tid >> 5] = s;
    __syncthreads();
    if (tid < 32) {
        float t = (tid < 16) ? sm[tid] : 0.f;
        #pragma unroll
        for (int o = 8; o; o >>= 1) t += __shfl_xor_sync(0xffffffffu, t, o);
        if (tid == 0) sm[0] = t;
    }
    __syncthreads();
    float inv = 1.f / sm[0];
    for (int idx = tid; idx < NSQ; idx += 512) ptr[idx] = expf(ptr[idx] - m) * inv;
}

// ---------------- ctx ----------------
__global__ void ctx_zero_kernel() {
    int id = blockIdx.x * blockDim.x + threadIdx.x;
    if (id < BB*NHEADS*256) g_ctx[id] = 0.f;
}
__global__ __launch_bounds__(256) void ctx_kernel()
{
    __shared__ float ka[16][129];
    __shared__ float va[16][129];
    int bh = blockIdx.x, chunk = blockIdx.y;
    int b = bh >> 2, h = bh & 3;
    int tid = threadIdx.x;
    int d = tid >> 4, e = tid & 15;
    const float* kbase = g_ks + (size_t)(b*CCH + h*16) * NSQ;
    const float* vbase = g_vs + (size_t)(b*CCH + h*16) * NSQ;
    float acc = 0.f;
    for (int sub = 0; sub < 8; sub++) {
        int n0 = chunk * 1024 + sub * 128;
        __syncthreads();
        #pragma unroll
        for (int q = tid; q < 2048; q += 256) {
            int r = q >> 7, t = q & 127;
            ka[r][t] = kbase[(size_t)r * NSQ + n0 + t];
            va[r][t] = vbase[(size_t)r * NSQ + n0 + t];
        }
        __syncthreads();
        #pragma unroll
        for (int t = 0; t < 128; t++) acc += ka[d][t] * va[e][t];
    }
    atomicAdd(&g_ctx[bh*256 + tid], acc);
}

// ---------------- q softmax(d) + ctx -> squeezed NHWC att ----------------
__global__ __launch_bounds__(256) void att_kernel()
{
    __shared__ float cs[16][17];
    int bh = blockIdx.y;
    int b = bh >> 2, h = bh & 3;
    int tid = threadIdx.x;
    int n = blockIdx.x * 256 + tid;
    cs[tid >> 4][tid & 15] = g_ctx[bh*256 + tid];
    __syncthreads();
    const float* qb = g_qs + (size_t)(b*CCH + h*16) * NSQ + n;
    float p[16];
    float m = -1e30f;
    #pragma unroll
    for (int d = 0; d < 16; d++) { p[d] = qb[(size_t)d * NSQ]; m = fmaxf(m, p[d]); }
    float s = 0.f;
    #pragma unroll
    for (int d = 0; d < 16; d++) { p[d] = expf(p[d] - m); s += p[d]; }
    float inv = 1.f / s;
    float va[16];
    #pragma unroll
    for (int e = 0; e < 16; e++) {
        float a = 0.f;
        #pragma unroll
        for (int d = 0; d < 16; d++) a += cs[d][e] * p[d];
        va[e] = a * inv;
    }
    float* pa = g_att + ((size_t)n + (size_t)b*NSQ) * CCH + h*16;
    #pragma unroll
    for (int g = 0; g < 4; g++)
        *reinterpret_cast<float4*>(pa + g*4) =
            make_float4(va[g*4], va[g*4+1], va[g*4+2], va[g*4+3]);
}

// ---------------- conv5 via warp-MMA, direct-LDG A, no per-tap syncs ----------------
#define C5_TOT (5*130*68*4)
__global__ __launch_bounds__(256) void conv5_mma(const float* __restrict__ bias)
{
    extern __shared__ float sm[];
    float* S5 = sm;                       // [r5][u'][ci] pad 68
    int tid = threadIdx.x;
    int warp = tid >> 5, lane = tid & 31;
    int gid = lane >> 2, tig = lane & 3;
    int mw = warp & 1, nw = warp >> 1;
    int y = blockIdx.x, ch = blockIdx.y, b = blockIdx.z;

    for (int q = tid; q < 5*130*16; q += 256) {
        int r5 = q / (130*16), rem = q % (130*16);
        int up = rem >> 4, cig = rem & 15;
        int r = y + r5 - 2, u = up - 1;
        float4 v = make_float4(0.f, 0.f, 0.f, 0.f);
        if (r >= 0 && r < HH && u >= 0 && u < WHF)
            v = rna4(*reinterpret_cast<const float4*>(
                g_att + ((size_t)b*NSQ + r*WHF + u) * CCH + cig*4));
        *reinterpret_cast<float4*>(&S5[(r5*130 + up)*68 + cig*4]) = v;
    }
    __syncthreads();

    float acc[2][2][4][4];
    #pragma unroll
    for (int t = 0; t < 2; t++)
        #pragma unroll
        for (int mt = 0; mt < 2; mt++)
            #pragma unroll
            for (int nt = 0; nt < 4; nt++)
                #pragma unroll
                for (int f = 0; f < 4; f++) acc[t][mt][nt][f] = 0.f;

    for (int dy = 0; dy < 5; dy++) {
        int r = y + dy - 2;
        if (r < 0 || r >= HH) continue;
        int rp = r & 1;
        #pragma unroll
        for (int dx = 0; dx < 5; dx++) {
            int t   = (r + dx) & 1;
            int off = (dx & 1) ? (rp ? (dx-3)/2 : (dx-1)/2) : (dx-2)/2;
            const float* Aw = g_w5 + ((dy*5 + dx)*128 + ch*64)*64;
            const float* Brow = &S5[dy*130*68 + (off + 1)*68];
            #pragma unroll
            for (int ks = 0; ks < 8; ks++) {
                int k = ks*8 + tig;
                u32 a[2][4];
                #pragma unroll
                for (int mt = 0; mt < 2; mt++) {
                    int m = mw*32 + mt*16 + gid;
                    a[mt][0] = __float_as_uint(__ldg(Aw + m*64 + k));
                    a[mt][1] = __float_as_uint(__ldg(Aw + (m+8)*64 + k));
                    a[mt][2] = __float_as_uint(__ldg(Aw + m*64 + k + 4));
                    a[mt][3] = __float_as_uint(__ldg(Aw + (m+8)*64 + k + 4));
                }
                #pragma unroll
                for (int nt = 0; nt < 4; nt++) {
                    int n = nw*32 + nt*8 + gid;
                    u32 bf[2];
                    bf[0] = __float_as_uint(Brow[n*68 + k]);
                    bf[1] = __float_as_uint(Brow[n*68 + k + 4]);
                    mma8(acc[t][0][nt], a[0], bf);
                    mma8(acc[t][1][nt], a[1], bf);
                }
            }
        }
    }
    #pragma unroll
    for (int mt = 0; mt < 2; mt++) {
        int co = ch*64 + mw*32 + mt*16 + gid;
        float b0 = bias[co], b8 = bias[co + 8];
        float* r0 = g_attn + ((size_t)(b*C2 + co)     * HH + y) * WWD;
        float* r8 = g_attn + ((size_t)(b*C2 + co + 8) * HH + y) * WWD;
        #pragma unroll
        for (int t = 0; t < 2; t++)
            #pragma unroll
            for (int nt = 0; nt < 4; nt++) {
                int w = nw*32 + nt*8 + 2*tig;
                int x = 2*w + t;
                float* a = acc[t][mt][nt];
                r0[x]     = a[0] + b0;
                r0[x + 2] = a[1] + b0;
                r8[x]     = a[2] + b8;
                r8[x + 2] = a[3] + b8;
            }
    }
}

// ---------------- mlp GEMM: M=128 co x N=128 px, K=KK, direct-LDG A ----------------
#define MM_TOT (128*132*4)
template<int KK, int ACT>   // ACT 1: gelu ; 2: bias+residual
__global__ __launch_bounds__(256) void mlp_mma(
    const float* __restrict__ inp, const float* __restrict__ wpre,
    const float* __restrict__ bias, float* __restrict__ outp)
{
    extern __shared__ float sm[];
    float* Bs = sm;   // [ci][px] pad 132
    int tid = threadIdx.x, warp = tid >> 5, lane = tid & 31;
    int gid = lane >> 2, tig = lane & 3;
    int mw = warp & 3, nw = warp >> 2;
    int P0 = blockIdx.x * 128, co_base = blockIdx.y * 128, b = blockIdx.z;

    float acc[2][8][4];
    #pragma unroll
    for (int mt = 0; mt < 2; mt++)
        #pragma unroll
        for (int nt = 0; nt < 8; nt++)
            #pragma unroll
            for (int f = 0; f < 4; f++) acc[mt][nt][f] = 0.f;

    for (int kc = 0; kc < KK/128; kc++) {
        if (kc) __syncthreads();
        for (int q = tid; q < 128*32; q += 256) {
            int ci = q >> 5, pg = q & 31;
            *reinterpret_cast<float4*>(&Bs[ci*132 + pg*4]) =
                rna4(*reinterpret_cast<const float4*>(
                    inp + (size_t)(b*KK + kc*128 + ci) * HWW + P0 + pg*4));
        }
        __syncthreads();
        const float* Aw = wpre + (size_t)co_base * KK + kc*128;
        #pragma unroll
        for (int ks = 0; ks < 16; ks++) {
            int k = ks*8 + tig;
            u32 a[2][4];
            #pragma unroll
            for (int mt = 0; mt < 2; mt++) {
                int m = mw*32 + mt*16 + gid;
                a[mt][0] = __float_as_uint(__ldg(Aw + (size_t)m*KK + k));
                a[mt][1] = __float_as_uint(__ldg(Aw + (size_t)(m+8)*KK + k));
                a[mt][2] = __float_as_uint(__ldg(Aw + (size_t)m*KK + k + 4));
                a[mt][3] = __float_as_uint(__ldg(Aw + (size_t)(m+8)*KK + k + 4));
            }
            #pragma unroll
            for (int nt = 0; nt < 8; nt++) {
                int n = nw*64 + nt*8 + gid;
                u32 bf[2];
                bf[0] = __float_as_uint(Bs[k*132 + n]);
                bf[1] = __float_as_uint(Bs[(k+4)*132 + n]);
                mma8(acc[0][nt], a[0], bf);
                mma8(acc[1][nt], a[1], bf);
            }
        }
    }
    int cout_tot = (ACT == 1) ? C4 : C2;
    #pragma unroll
    for (int mt = 0; mt < 2; mt++) {
        int col = mw*32 + mt*16 + gid;
        int co = co_base + col;
        float b0 = bias[co], b8 = bias[co + 8];
        float* o0 = outp + (size_t)(b*cout_tot + co)     * HWW + P0;
        float* o8 = outp + (size_t)(b*cout_tot + co + 8) * HWW + P0;
        const float* r0 = g_attn + (size_t)(b*C2 + col)     * HWW + P0;
        const float* r8 = g_attn + (size_t)(b*C2 + col + 8) * HWW + P0;
        #pragma unroll
        for (int nt = 0; nt < 8; nt++) {
            int px = nw*64 + nt*8 + 2*tig;
            float* a = acc[mt][nt];
            if (ACT == 1) {
                *reinterpret_cast<float2*>(o0 + px) =
                    make_float2(gelu_f(a[0] + b0), gelu_f(a[1] + b0));
                *reinterpret_cast<float2*>(o8 + px) =
                    make_float2(gelu_f(a[2] + b8), gelu_f(a[3] + b8));
            } else {
                float2 v0 = *reinterpret_cast<const float2*>(r0 + px);
                float2 v8 = *reinterpret_cast<const float2*>(r8 + px);
                *reinterpret_cast<float2*>(o0 + px) =
                    make_float2(a[0] + b0 + v0.x, a[1] + b0 + v0.y);
                *reinterpret_cast<float2*>(o8 + px) =
                    make_float2(a[2] + b8 + v8.x, a[3] + b8 + v8.y);
            }
        }
    }
}

// ---------------- depthwise 3x3 (256 ch) + gelu, 4 outputs/thread ----------------
__global__ void dw_gelu_kernel(const float* __restrict__ in,
                               const float* __restrict__ wt,
                               const float* __restrict__ bias,
                               float* __restrict__ out)
{
    int id = blockIdx.x * blockDim.x + threadIdx.x;
    if (id >= BB*C4*HH*64) return;
    int x4 = id & 63;
    int i  = (id >> 6) & 255;
    int c  = (id >> 14) & 255;
    int b  = id >> 22;
    int x0 = x4 * 4;
    float w[9];
    #pragma unroll
    for (int t = 0; t < 9; t++) w[t] = __ldg(&wt[c*9 + t]);
    const float* base = in + (size_t)(b*C4 + c) * HWW;

    float row[3][6];
    bool fast = (x0 >= 1) && (x0 + 4 <= 255);
    #pragma unroll
    for (int dy = 0; dy < 3; dy++) {
        int yy = i + dy - 1;
        if (yy < 0 || yy >= HH) {
            #pragma unroll
            for (int s = 0; s < 6; s++) row[dy][s] = 0.f;
        } else {
            const float* rp = base + yy*WWD;
            if (fast) {
                #pragma unroll
                for (int s = 0; s < 6; s++) row[dy][s] = __ldg(rp + x0 - 1 + s);
            } else {
                #pragma unroll
                for (int s = 0; s < 6; s++) {
                    int xx = x0 - 1 + s;
                    row[dy][s] = (xx >= 0 && xx < WWD) ? __ldg(rp + xx) : 0.f;
                }
            }
        }
    }
    float bb = bias[c];
    float4 o;
    float* ov = reinterpret_cast<float*>(&o);
    #pragma unroll
    for (int s = 0; s < 4; s++) {
        float acc = bb;
        #pragma unroll
        for (int dy = 0; dy < 3; dy++)
            #pragma unroll
            for (int dx = 0; dx < 3; dx++)
                acc += w[dy*3 + dx] * row[dy][s + dx];
        ov[s] = gelu_f(acc);
    }
    *reinterpret_cast<float4*>(out + (size_t)(b*C4 + c) * HWW + i*WWD + x0) = o;
}

// ---------------- launch ----------------
extern "C" void kernel_launch(void* const* d_in, const int* in_sizes, int n_in,
                              void* d_out, int out_size)
{
    const float* x1   = (const float*)d_in[0];
    const float* x2   = (const float*)d_in[1];
    const float* q1_w = (const float*)d_in[2];
    const float* q1_b = (const float*)d_in[3];
    const float* q2_w = (const float*)d_in[4];
    const float* q2_b = (const float*)d_in[5];
    const float* k1_w = (const float*)d_in[6];
    const float* k1_b = (const float*)d_in[7];
    const float* k2_w = (const float*)d_in[8];
    const float* k2_b = (const float*)d_in[9];
    const float* v1_w = (const float*)d_in[10];
    const float* v1_b = (const float*)d_in[11];
    const float* v2_w = (const float*)d_in[12];
    const float* v2_b = (const float*)d_in[13];
    const float* r_w  = (const float*)d_in[14];
    const float* r_b  = (const float*)d_in[15];
    const float* m1_w = (const float*)d_in[16];
    const float* m1_b = (const float*)d_in[17];
    const float* m2_w = (const float*)d_in[18];
    const float* m2_b = (const float*)d_in[19];
    const float* m3_w = (const float*)d_in[20];
    const float* m3_b = (const float*)d_in[21];
    float* out = (float*)d_out;

    float *p_q1, *p_k1, *p_v1, *p_qs, *p_ks, *p_vs, *p_attn, *p_m1, *p_m2;
    float *p_wq, *p_wk, *p_wv, *p_wm1, *p_wm3;
    cudaGetSymbolAddress((void**)&p_q1, g_q1);
    cudaGetSymbolAddress((void**)&p_k1, g_k1);
    cudaGetSymbolAddress((void**)&p_v1, g_v1);
    cudaGetSymbolAddress((void**)&p_qs, g_qs);
    cudaGetSymbolAddress((void**)&p_ks, g_ks);
    cudaGetSymbolAddress((void**)&p_vs, g_vs);
    cudaGetSymbolAddress((void**)&p_attn, g_attn);
    cudaGetSymbolAddress((void**)&p_m1, g_m1);
    cudaGetSymbolAddress((void**)&p_m2, g_m2);
    cudaGetSymbolAddress((void**)&p_wq, g_wq);
    cudaGetSymbolAddress((void**)&p_wk, g_wk);
    cudaGetSymbolAddress((void**)&p_wv, g_wv);
    cudaGetSymbolAddress((void**)&p_wm1, g_wm1);
    cudaGetSymbolAddress((void**)&p_wm3, g_wm3);

    cudaFuncSetAttribute(conv5_mma, cudaFuncAttributeMaxDynamicSharedMemorySize, C5_TOT);
    cudaFuncSetAttribute(mlp_mma<128,1>, cudaFuncAttributeMaxDynamicSharedMemorySize, MM_TOT);
    cudaFuncSetAttribute(mlp_mma<256,2>, cudaFuncAttributeMaxDynamicSharedMemorySize, MM_TOT);

    prep_w5<<<800, 256>>>(r_w);
    prep_rna<<<16, 256>>>(q1_w, p_wq, 4096);
    prep_rna<<<16, 256>>>(k1_w, p_wk, 4096);
    prep_rna<<<16, 256>>>(v1_w, p_wv, 4096);
    prep_rna<<<128, 256>>>(m1_w, p_wm1, C4*C2);
    prep_rna<<<128, 256>>>(m3_w, p_wm3, C2*C4);

    dim3 g1(HWW/128, 1, BB);
    qkv_mma<1><<<g1, 256>>>(x1, p_wq, q1_b, p_q1);
    qkv_mma<2><<<g1, 256>>>(x1, p_wk, k1_b, p_k1);
    qkv_mma<0><<<g1, 256>>>(x2, p_wv, v1_b, p_v1);

    int ndw = BB*CCH*HH*32;
    dw_squeeze_kernel<<<ndw/256, 256>>>(p_q1, q2_w, q2_b, p_qs, 0);
    dw_squeeze_kernel<<<ndw/256, 256>>>(p_k1, k2_w, k2_b, p_ks, 1);
    dw_squeeze_kernel<<<ndw/256, 256>>>(p_v1, v2_w, v2_b, p_vs, 1);

    softmax_k_kernel<<<BB*CCH, 512>>>(p_ks);
    ctx_zero_kernel<<<16, 256>>>();
    ctx_kernel<<<dim3(BB*NHEADS, 32), 256>>>();
    att_kernel<<<dim3(NSQ/256, BB*NHEADS), 256>>>();

    conv5_mma<<<dim3(HH, 2, BB), 256, C5_TOT>>>(r_b);

    mlp_mma<128,1><<<dim3(HWW/128, 2, BB), 256, MM_TOT>>>(p_attn, p_wm1, m1_b, p_m1);
    dw_gelu_kernel<<<(BB*C4*HH*64)/256, 256>>>(p_m1, m2_w, m2_b, p_m2);
    mlp_mma<256,2><<<dim3(HWW/128, 1, BB), 256, MM_TOT>>>(p_m2, p_wm3, m3_b, out);
}